// round 2
// baseline (speedup 1.0000x reference)
#include <cuda_runtime.h>
#include <cuda_bf16.h>
#include <cstdint>

#define N_DE 12288
#define M_X  2048
#define DIM  128
#define TILE 128
#define T_BLOCKS (N_DE / TILE)                      // 96
#define KXX_BLOCKS (T_BLOCKS * (T_BLOCKS + 1) / 2)  // 4656
#define M_TILES (M_X / TILE)                        // 16
#define KXY_BLOCKS (T_BLOCKS * M_TILES)             // 1536
#define SMEM_BYTES (2 * TILE * DIM * 2 + 3 * TILE * 4)  // 67072

// -0.5/512 * log2(e), -0.5/10 * log2(e)
__device__ const float C1 = -0.0014088819735243784f;
__device__ const float C2 = -0.07213475204444817f;

__device__ __align__(16) __nv_bfloat16 g_De_bf[N_DE * DIM];
__device__ __align__(16) __nv_bfloat16 g_X_bf[M_X * DIM];
__device__ float  g_sq_de[N_DE];
__device__ float  g_sq_x[M_X];
__device__ double g_kxx;
__device__ float  g_kxy[M_X];

__device__ __forceinline__ float ex2f(float x) {
    float y;
    asm("ex2.approx.ftz.f32 %0, %1;" : "=f"(y) : "f"(x));
    return y;
}

// ---------------- prep: fp32 -> bf16 + row squared norms + zero accumulators --------
__global__ void prep_kernel(const float* __restrict__ De, const float* __restrict__ X) {
    if (blockIdx.x == 0) {
        for (int i = threadIdx.x; i < M_X; i += blockDim.x) g_kxy[i] = 0.f;
        if (threadIdx.x == 0) g_kxx = 0.0;
    }
    int warp = (blockIdx.x * blockDim.x + threadIdx.x) >> 5;
    int lane = threadIdx.x & 31;
    if (warp >= N_DE + M_X) return;

    const float* src;
    __nv_bfloat16* dst;
    float* sq;
    if (warp < N_DE) {
        src = De + (size_t)warp * DIM;
        dst = g_De_bf + (size_t)warp * DIM;
        sq  = g_sq_de + warp;
    } else {
        int r = warp - N_DE;
        src = X + (size_t)r * DIM;
        dst = g_X_bf + (size_t)r * DIM;
        sq  = g_sq_x + r;
    }
    float4 v = ((const float4*)src)[lane];
    float s = v.x * v.x + v.y * v.y + v.z * v.z + v.w * v.w;
    __nv_bfloat162 p0 = __float22bfloat162_rn(make_float2(v.x, v.y));
    __nv_bfloat162 p1 = __float22bfloat162_rn(make_float2(v.z, v.w));
    uint2 u;
    u.x = *(unsigned*)&p0;
    u.y = *(unsigned*)&p1;
    ((uint2*)dst)[lane] = u;
#pragma unroll
    for (int o = 16; o; o >>= 1) s += __shfl_xor_sync(0xffffffffu, s, o);
    if (lane == 0) *sq = s;
}

// ---------------- shared helpers ----------------------------------------------------
__device__ __forceinline__ unsigned sw_addr(unsigned sbase, int r, int c) {
    int chunk = (c >> 3) ^ (r & 7);
    return sbase + (unsigned)((r << 8) + (chunk << 4) + ((c & 7) << 1));
}

__device__ __forceinline__ void ldm4(unsigned addr, unsigned& r0, unsigned& r1,
                                     unsigned& r2, unsigned& r3) {
    asm volatile("ldmatrix.sync.aligned.m8n8.x4.shared.b16 {%0,%1,%2,%3}, [%4];"
                 : "=r"(r0), "=r"(r1), "=r"(r2), "=r"(r3)
                 : "r"(addr));
}

__device__ __forceinline__ void mma16816(float* c, unsigned a0, unsigned a1, unsigned a2,
                                         unsigned a3, unsigned b0, unsigned b1) {
    asm volatile(
        "mma.sync.aligned.m16n8k16.row.col.f32.bf16.bf16.f32 "
        "{%0,%1,%2,%3},{%4,%5,%6,%7},{%8,%9},{%0,%1,%2,%3};"
        : "+f"(c[0]), "+f"(c[1]), "+f"(c[2]), "+f"(c[3])
        : "r"(a0), "r"(a1), "r"(a2), "r"(a3), "r"(b0), "r"(b1));
}

// 128x128 bf16 tile: global (row-major, 16 uint4/row) -> swizzled smem
__device__ __forceinline__ void load_tile(__nv_bfloat16* s, const __nv_bfloat16* g) {
    int t = threadIdx.x;
#pragma unroll
    for (int i = 0; i < 8; i++) {
        int id = t + i * 256;
        int r = id >> 4, c = id & 15;
        uint4 v = ((const uint4*)g)[(r << 4) + c];
        int pc = c ^ (r & 7);
        ((uint4*)s)[(r << 4) + pc] = v;
    }
}

// ---------------- merged kxx/kxy kernel with MMA/MUFU interleave --------------------
// Each warp: 64x32 output tile, processed in 4 passes over mi (16 rows each).
// Pass mi computes MMAs for rows [mi*16, mi*16+16) while retiring the EX2
// epilogue of pass mi-1, 2 pairs per k-step. Last pass's epilogue is the tail.
template <bool IS_KXX>
__device__ __forceinline__ void tile_work(
    const __nv_bfloat16* gA, const __nv_bfloat16* gB,
    const float* gsqa, const float* gsqb,
    char* smem_raw, float kxx_weight, float* kxy_out /*g_kxy+bm*128 or null*/) {

    __nv_bfloat16* As = (__nv_bfloat16*)smem_raw;
    __nv_bfloat16* Bs = As + TILE * DIM;
    float* sqa = (float*)(Bs + TILE * DIM);
    float* sqb = sqa + TILE;
    float* srow = sqb + TILE;
    __shared__ float s_bsum;

    int t = threadIdx.x, lane = t & 31, warp = t >> 5;

    if (IS_KXX) { if (t == 0) s_bsum = 0.f; }
    load_tile(As, gA);
    load_tile(Bs, gB);
    if (t < 128) {
        sqa[t] = gsqa[t];
        if (!IS_KXX) srow[t] = 0.f;
    } else {
        sqb[t - 128] = gsqb[t - 128];
    }
    __syncthreads();

    int wm = (warp >> 2) * 64;
    int wn = (warp & 3) * 32;
    unsigned sA = (unsigned)__cvta_generic_to_shared(As);
    unsigned sB = (unsigned)__cvta_generic_to_shared(Bs);

    int lrA = lane & 15, lcA = (lane >> 4) << 3;
    int grp = lane >> 3, w8 = lane & 7;
    int rB = ((grp & 2) << 2) + w8;
    int cB = (grp & 1) << 3;

    int r0 = wm + (lane >> 2);
    int c0 = wn + ((lane & 3) << 1);
    float sc0[4], sc1[4];
#pragma unroll
    for (int ni = 0; ni < 4; ni++) {
        sc0[ni] = sqb[c0 + ni * 8];
        sc1[ni] = sqb[c0 + ni * 8 + 1];
    }

    float accP[4][4];   // previous pass accumulators (pairs being retired)
    float srP0 = 0.f, srP1 = 0.f;
    float ssum = 0.f;   // kxx scalar sum
    float p0 = 0.f, p1 = 0.f;  // kxy per-row partials for current retiring mi

#pragma unroll
    for (int mi = 0; mi < 4; mi++) {
        float accC[4][4];
#pragma unroll
        for (int ni = 0; ni < 4; ni++)
#pragma unroll
            for (int e = 0; e < 4; e++) accC[ni][e] = 0.f;

#pragma unroll
        for (int kk = 0; kk < 8; kk++) {
            int k0 = kk << 4;
            unsigned a0, a1, a2, a3;
            ldm4(sw_addr(sA, wm + mi * 16 + lrA, k0 + lcA), a0, a1, a2, a3);
            unsigned b[4][2];
            {
                unsigned q0, q1, q2, q3;
                ldm4(sw_addr(sB, wn + rB, k0 + cB), q0, q1, q2, q3);
                b[0][0] = q0; b[0][1] = q1; b[1][0] = q2; b[1][1] = q3;
                ldm4(sw_addr(sB, wn + 16 + rB, k0 + cB), q0, q1, q2, q3);
                b[2][0] = q0; b[2][1] = q1; b[3][0] = q2; b[3][1] = q3;
            }
#pragma unroll
            for (int ni = 0; ni < 4; ni++)
                mma16816(accC[ni], a0, a1, a2, a3, b[ni][0], b[ni][1]);

            if (mi > 0) {
                // retire 2 pairs of the previous pass, interleaved with the MMAs
#pragma unroll
                for (int pp = 0; pp < 2; pp++) {
                    int p = kk * 2 + pp;
                    int ni = p >> 2, e = p & 3;
                    float sr = (e & 2) ? srP1 : srP0;
                    float sc = (e & 1) ? sc1[ni] : sc0[ni];
                    float d2 = fmaf(-2.f, accP[ni][e], sr + sc);
                    float v = ex2f(C1 * d2) + ex2f(C2 * d2);
                    if (IS_KXX) ssum += v;
                    else { if (e & 2) p1 += v; else p0 += v; }
                }
            }
        }
        if (!IS_KXX && mi > 0) {
            // flush row partials for rows of pass mi-1
            float v0 = p0, v1 = p1;
            v0 += __shfl_xor_sync(0xffffffffu, v0, 1);
            v0 += __shfl_xor_sync(0xffffffffu, v0, 2);
            v1 += __shfl_xor_sync(0xffffffffu, v1, 1);
            v1 += __shfl_xor_sync(0xffffffffu, v1, 2);
            if ((lane & 3) == 0) {
                int row = wm + (mi - 1) * 16 + (lane >> 2);
                atomicAdd(&srow[row], v0);
                atomicAdd(&srow[row + 8], v1);
            }
            p0 = 0.f; p1 = 0.f;
        }
        // rotate current -> previous
#pragma unroll
        for (int ni = 0; ni < 4; ni++)
#pragma unroll
            for (int e = 0; e < 4; e++) accP[ni][e] = accC[ni][e];
        srP0 = sqa[r0 + mi * 16];
        srP1 = sqa[r0 + mi * 16 + 8];
    }

    // tail: epilogue of pass mi=3
#pragma unroll
    for (int p = 0; p < 16; p++) {
        int ni = p >> 2, e = p & 3;
        float sr = (e & 2) ? srP1 : srP0;
        float sc = (e & 1) ? sc1[ni] : sc0[ni];
        float d2 = fmaf(-2.f, accP[ni][e], sr + sc);
        float v = ex2f(C1 * d2) + ex2f(C2 * d2);
        if (IS_KXX) ssum += v;
        else { if (e & 2) p1 += v; else p0 += v; }
    }

    if (IS_KXX) {
#pragma unroll
        for (int o = 16; o; o >>= 1) ssum += __shfl_xor_sync(0xffffffffu, ssum, o);
        if (lane == 0) atomicAdd(&s_bsum, ssum);
        __syncthreads();
        if (t == 0) atomicAdd(&g_kxx, (double)kxx_weight * (double)s_bsum);
    } else {
        float v0 = p0, v1 = p1;
        v0 += __shfl_xor_sync(0xffffffffu, v0, 1);
        v0 += __shfl_xor_sync(0xffffffffu, v0, 2);
        v1 += __shfl_xor_sync(0xffffffffu, v1, 1);
        v1 += __shfl_xor_sync(0xffffffffu, v1, 2);
        if ((lane & 3) == 0) {
            int row = wm + 3 * 16 + (lane >> 2);
            atomicAdd(&srow[row], v0);
            atomicAdd(&srow[row + 8], v1);
        }
        __syncthreads();
        if (t < 128) atomicAdd(&kxy_out[t], srow[t]);
    }
}

__global__ void __launch_bounds__(256, 2) mmd_kernel() {
    extern __shared__ char smem_raw[];
    int blk = blockIdx.x;
    if (blk < KXX_BLOCKS) {
        // triangular decode: blk -> (bi, bj), bi <= bj
        int tb = blk;
        const int Tn = T_BLOCKS;
        int bi = (int)((2 * Tn + 1 -
                        sqrtf((float)((2 * Tn + 1) * (2 * Tn + 1) - 8 * tb))) * 0.5f);
        while (bi * Tn - bi * (bi - 1) / 2 > tb) bi--;
        while ((bi + 1) * Tn - (bi + 1) * bi / 2 <= tb) bi++;
        int bj = bi + (tb - (bi * Tn - bi * (bi - 1) / 2));
        tile_work<true>(g_De_bf + (size_t)bi * TILE * DIM,
                        g_De_bf + (size_t)bj * TILE * DIM,
                        g_sq_de + bi * TILE, g_sq_de + bj * TILE,
                        smem_raw, (bi == bj) ? 1.f : 2.f, nullptr);
    } else {
        int q = blk - KXX_BLOCKS;
        int bm = q / T_BLOCKS;
        int bn = q % T_BLOCKS;
        tile_work<false>(g_X_bf + (size_t)bm * TILE * DIM,
                         g_De_bf + (size_t)bn * TILE * DIM,
                         g_sq_x + bm * TILE, g_sq_de + bn * TILE,
                         smem_raw, 0.f, g_kxy + bm * TILE);
    }
}

// ---------------- finalize -----------------------------------------------------------
__global__ void final_kernel(float* __restrict__ out) {
    int m = blockIdx.x * blockDim.x + threadIdx.x;
    if (m < M_X) {
        float kxx_mean = (float)(g_kxx / ((double)N_DE * (double)N_DE));
        out[m] = kxx_mean + 2.0f - 2.0f * (g_kxy[m] * (1.0f / (float)N_DE));
    }
}

extern "C" void kernel_launch(void* const* d_in, const int* in_sizes, int n_in,
                              void* d_out, int out_size) {
    const float* De = (const float*)d_in[0];
    const float* X  = (const float*)d_in[1];
    float* out = (float*)d_out;

    cudaFuncSetAttribute(mmd_kernel, cudaFuncAttributeMaxDynamicSharedMemorySize, SMEM_BYTES);

    prep_kernel<<<(N_DE + M_X) / 4, 128>>>(De, X);
    mmd_kernel<<<KXX_BLOCKS + KXY_BLOCKS, 256, SMEM_BYTES>>>();
    final_kernel<<<(M_X + 127) / 128, 128>>>(out);
}